// round 11
// baseline (speedup 1.0000x reference)
#include <cuda_runtime.h>

// TSModel: 2-layer LSTM (layer0: 1->64, layer1: 64->1; layer1 input = c0,
// per-step output = c1). B=2048, T=1024, fp32.
//
// R11: 2 gate rows per thread (halves L1 wavefront traffic, the measured
// binder at 81%) fused with R9's one-barrier warp-local topology.
//  - 293 CTAs x 128 threads, MROWS=7, 2 CTAs/SM.
//  - warp w owns units [16w,16w+16); lane l -> unit 16w+(l>>1), gate pair
//    p=(l&1): gate rows {2p, 2p+1}. 128 packed-f32x2 weight regs/thread;
//    each LDS.128 of h feeds 8 fma.rn.f32x2.
//  - Phase A -> Gs (STS.64) -> __syncwarp -> Phase B (warp-local, c in regs,
//    h to double-buffered Hs) -> ONE __syncthreads.
//  - Layer-1 pipelined one step behind at loop top (warp w: rows w, w+4).

#define BATCH 2048
#define TSTEPS 1024
#define UNITS 64
#define MROWS 7
#define NCTA ((BATCH + MROWS - 1) / MROWS)   // 293
#define NTHR 128

typedef unsigned long long u64;

__device__ __forceinline__ u64 pack2(float lo, float hi) {
    u64 r;
    asm("mov.b64 %0, {%1, %2};" : "=l"(r) : "f"(lo), "f"(hi));
    return r;
}
__device__ __forceinline__ void unpack2(u64 v, float& lo, float& hi) {
    asm("mov.b64 {%0, %1}, %2;" : "=f"(lo), "=f"(hi) : "l"(v));
}
__device__ __forceinline__ u64 fma2(u64 a, u64 b, u64 c) {
    u64 d;
    asm("fma.rn.f32x2 %0, %1, %2, %3;" : "=l"(d) : "l"(a), "l"(b), "l"(c));
    return d;
}
__device__ __forceinline__ float rcp_apx(float x) {
    float r;
    asm("rcp.approx.f32 %0, %1;" : "=f"(r) : "f"(x));
    return r;
}
// sigmoid(x) = 1 / (1 + e^-x)
__device__ __forceinline__ float sig_f(float x) {
    return rcp_apx(1.0f + __expf(-x));
}
// tanh(x) = 1 - 2/(1 + e^{2x})
__device__ __forceinline__ float tanh_f(float x) {
    return fmaf(-2.0f, rcp_apx(1.0f + __expf(x + x)), 1.0f);
}

__global__ void __launch_bounds__(NTHR, 2)
lstm_kernel(const float* __restrict__ in,
            const float* __restrict__ Wih0, const float* __restrict__ Whh0,
            const float* __restrict__ bih0, const float* __restrict__ bhh0,
            const float* __restrict__ Wih1, const float* __restrict__ Whh1,
            const float* __restrict__ bih1, const float* __restrict__ bhh1,
            float* __restrict__ out) {
    __shared__ __align__(16) float Hs[2][MROWS][UNITS];      // h double-buffer
    __shared__ __align__(16) float Cs[2][MROWS][UNITS];      // c for layer-1
    __shared__ __align__(16) float Gs[MROWS][UNITS][4];      // gates i,f,g,o
    __shared__ __align__(16) float Xs[MROWS][TSTEPS];

    const int tid = threadIdx.x;
    const int lane = tid & 31;
    const int wid = tid >> 5;                 // 0..3
    const int r0 = blockIdx.x * MROWS;
    const int mrows = min(MROWS, BATCH - r0);

    // ---- gate identity: unit ul, gate pair p -> gate rows 2p, 2p+1 ----
    const int ul = 16 * wid + (lane >> 1);
    const int p = lane & 1;
    const int rowA = (2 * p) * UNITS + ul;
    const int rowB = (2 * p + 1) * UNITS + ul;

    u64 wA[32], wB[32];
    {
        const float2* wra = (const float2*)(Whh0 + rowA * UNITS);
        const float2* wrb = (const float2*)(Whh0 + rowB * UNITS);
#pragma unroll
        for (int k = 0; k < 32; k++) {
            float2 va = wra[k];
            float2 vb = wrb[k];
            wA[k] = pack2(va.x, va.y);
            wB[k] = pack2(vb.x, vb.y);
        }
    }
    const float wxA = Wih0[rowA];
    const float wxB = Wih0[rowB];
    const float bsA = bih0[rowA] + bhh0[rowA];
    const float bsB = bih0[rowB] + bhh0[rowB];

    // ---- Phase-B identity: round r -> task (m = 2r+(lane>>4), unit uB) ----
    const int uB = 16 * wid + (lane & 15);
    const int mOff = lane >> 4;               // 0 or 1
    float creg[4] = {0.f, 0.f, 0.f, 0.f};

    // ---- Layer-1 identity: warp wid handles rows wid and wid+4 ----
    const int g1i = lane & 3;
    const int s1 = lane >> 2;
    float wi1[8];
#pragma unroll
    for (int k = 0; k < 8; k++) wi1[k] = Wih1[g1i * UNITS + s1 + 8 * k];
    const float whh1g = Whh1[g1i];
    const float b1g = bih1[g1i] + bhh1[g1i];
    float h1a = 0.f, c1a = 0.f, h1b = 0.f, c1b = 0.f;

    // Stage input rows into SMEM (coalesced float4 copy)
    {
        const float4* src = (const float4*)(in + (size_t)r0 * TSTEPS);
        float4* dst = (float4*)&Xs[0][0];
        const int n4 = mrows * (TSTEPS / 4);
        for (int i = tid; i < n4; i += NTHR) dst[i] = src[i];
    }
    // Zero both h buffers
    for (int i = tid; i < 2 * MROWS * UNITS; i += NTHR) (&Hs[0][0][0])[i] = 0.0f;
    __syncthreads();

    // ---- time loop: one __syncthreads per step ----
    for (int it = 0; it < TSTEPS; it++) {
        const int rb = it & 1;
        const int wb = rb ^ 1;

        // Layer-1 for step it-1 (pipelined; Cs[(it-1)&1] ordered by barrier)
        if (it > 0) {
            const int pb = (it - 1) & 1;
#pragma unroll
            for (int rr = 0; rr < 2; rr++) {
                const int m = wid + 4 * rr;
                if (m < mrows) {
                    float h1 = rr ? h1b : h1a;
                    float c1 = rr ? c1b : c1a;
                    float acc = 0.0f;
#pragma unroll
                    for (int k = 0; k < 8; k++)
                        acc = fmaf(wi1[k], Cs[pb][m][s1 + 8 * k], acc);
                    acc += __shfl_xor_sync(0xffffffffu, acc, 4);
                    acc += __shfl_xor_sync(0xffffffffu, acc, 8);
                    acc += __shfl_xor_sync(0xffffffffu, acc, 16);
                    acc += fmaf(whh1g, h1, b1g);
                    const float gi = __shfl_sync(0xffffffffu, acc, 0);
                    const float gf = __shfl_sync(0xffffffffu, acc, 1);
                    const float gg = __shfl_sync(0xffffffffu, acc, 2);
                    const float go = __shfl_sync(0xffffffffu, acc, 3);
                    c1 = sig_f(gf) * c1 + sig_f(gi) * tanh_f(gg);
                    h1 = sig_f(go) * tanh_f(c1);
                    if (lane == 0) out[(size_t)(r0 + m) * TSTEPS + (it - 1)] = c1;
                    if (rr) { h1b = h1; c1b = c1; } else { h1a = h1; c1a = c1; }
                }
            }
        }

        // Phase A: 2 gate rows per thread, every batch row
#pragma unroll
        for (int m = 0; m < MROWS; m++) {
            if (m < mrows) {
                const float xv = Xs[m][it];
                u64 axA = pack2(fmaf(xv, wxA, bsA), 0.f), ayA = 0ULL;
                u64 axB = pack2(fmaf(xv, wxB, bsB), 0.f), ayB = 0ULL;
                const ulonglong2* hp = (const ulonglong2*)&Hs[rb][m][0];
#pragma unroll
                for (int k = 0; k < 16; k++) {
                    ulonglong2 hv = hp[k];    // LDS.128 broadcast -> 4 FMA2 x2
                    axA = fma2(wA[2 * k], hv.x, axA);
                    ayA = fma2(wA[2 * k + 1], hv.y, ayA);
                    axB = fma2(wB[2 * k], hv.x, axB);
                    ayB = fma2(wB[2 * k + 1], hv.y, ayB);
                }
                float a, b, c, d;
                unpack2(axA, a, b);
                unpack2(ayA, c, d);
                const float sA = (a + b) + (c + d);
                unpack2(axB, a, b);
                unpack2(ayB, c, d);
                const float sB = (a + b) + (c + d);
                float2 st;
                st.x = sA;
                st.y = sB;
                *(float2*)&Gs[m][ul][2 * p] = st;    // STS.64
            }
        }
        __syncwarp();

        // Phase B: 4 rounds of warp-local activations (112 tasks / warp)
#pragma unroll
        for (int r = 0; r < 4; r++) {
            const int m = 2 * r + mOff;
            if (m < mrows) {
                const float4 gv = *(const float4*)&Gs[m][uB][0];
                const float cn = sig_f(gv.y) * creg[r] + sig_f(gv.x) * tanh_f(gv.z);
                const float hn = sig_f(gv.w) * tanh_f(cn);
                creg[r] = cn;
                Hs[wb][m][uB] = hn;
                Cs[rb][m][uB] = cn;
            }
        }
        __syncthreads();
    }

    // Epilogue: layer-1 for the final step (TSTEPS-1)
    {
        const int pb = (TSTEPS - 1) & 1;
#pragma unroll
        for (int rr = 0; rr < 2; rr++) {
            const int m = wid + 4 * rr;
            if (m < mrows) {
                float h1 = rr ? h1b : h1a;
                float c1 = rr ? c1b : c1a;
                float acc = 0.0f;
#pragma unroll
                for (int k = 0; k < 8; k++)
                    acc = fmaf(wi1[k], Cs[pb][m][s1 + 8 * k], acc);
                acc += __shfl_xor_sync(0xffffffffu, acc, 4);
                acc += __shfl_xor_sync(0xffffffffu, acc, 8);
                acc += __shfl_xor_sync(0xffffffffu, acc, 16);
                acc += fmaf(whh1g, h1, b1g);
                const float gi = __shfl_sync(0xffffffffu, acc, 0);
                const float gf = __shfl_sync(0xffffffffu, acc, 1);
                const float gg = __shfl_sync(0xffffffffu, acc, 2);
                const float go = __shfl_sync(0xffffffffu, acc, 3);
                c1 = sig_f(gf) * c1 + sig_f(gi) * tanh_f(gg);
                if (lane == 0) out[(size_t)(r0 + m) * TSTEPS + (TSTEPS - 1)] = c1;
            }
        }
    }
}

extern "C" void kernel_launch(void* const* d_in, const int* in_sizes, int n_in,
                              void* d_out, int out_size) {
    (void)in_sizes; (void)n_in; (void)out_size;
    lstm_kernel<<<NCTA, NTHR>>>(
        (const float*)d_in[0],  // input (2048,1024)
        (const float*)d_in[1],  // W_ih0 (256,1)
        (const float*)d_in[2],  // W_hh0 (256,64)
        (const float*)d_in[3],  // b_ih0 (256)
        (const float*)d_in[4],  // b_hh0 (256)
        (const float*)d_in[5],  // W_ih1 (4,64)
        (const float*)d_in[6],  // W_hh1 (4,1)
        (const float*)d_in[7],  // b_ih1 (4)
        (const float*)d_in[8],  // b_hh1 (4)
        (float*)d_out);         // out (2048,1024)
}